// round 2
// baseline (speedup 1.0000x reference)
#include <cuda_runtime.h>
#include <cuda_fp16.h>
#include <cuda_fp8.h>
#include <cstdint>

using u32 = unsigned int;

#define KDIM 1024
#define NOUT 58
#define NCLS 12
#define BM   128
#define BK   32
#define NCH  32          // 1024 / 32
#define STG  4

#define XS_STAGE_F32 (128 * 32)            // 16 KB per stage
#define WS_STAGE_U32 (64 * 20)             // 5 KB per stage (padded pitch 80B)
#define WS_OFF_BYTES (STG * XS_STAGE_F32 * 4)                  // 65536
#define SMEM_BYTES   (WS_OFF_BYTES + STG * WS_STAGE_U32 * 4)   // 86016

// ---------------- device scratch ----------------
__device__ __half g_w1q[64 * 1024];   // e4m3-valued W1 as f16, K-permuted, rows 58..63 zero
__device__ float  g_w2f[64 * 16];     // e4m3-valued W2 transposed [d][c], zero padded
__device__ float  g_bn[3 * 64];       // [inv | mean | beta]

// ---------------- helpers ----------------
__device__ __forceinline__ u32 q2h(float a, float b) {
    __nv_fp8x2_storage_t f8 =
        __nv_cvt_float2_to_fp8x2(make_float2(a, b), __NV_SATFINITE, __NV_E4M3);
    __half2_raw h2 = __nv_cvt_fp8x2_to_halfraw2(f8, __NV_E4M3);
    return (u32)h2.x | ((u32)h2.y << 16);
}

__device__ __forceinline__ float qf(float a) {
    __nv_fp8_storage_t f8 = __nv_cvt_float_to_fp8(a, __NV_SATFINITE, __NV_E4M3);
    __half_raw hr = __nv_cvt_fp8_to_halfraw(f8, __NV_E4M3);
    return __half2float(__half(hr));
}

__device__ __forceinline__ void mma16816(float* c, const u32* a, const u32* b) {
    asm volatile(
        "mma.sync.aligned.m16n8k16.row.col.f32.f16.f16.f32 "
        "{%0,%1,%2,%3}, {%4,%5,%6,%7}, {%8,%9}, {%0,%1,%2,%3};\n"
        : "+f"(c[0]), "+f"(c[1]), "+f"(c[2]), "+f"(c[3])
        : "r"(a[0]), "r"(a[1]), "r"(a[2]), "r"(a[3]), "r"(b[0]), "r"(b[1]));
}

#define CPA16(d, s)  asm volatile("cp.async.cg.shared.global [%0], [%1], 16;\n" :: "r"(d), "l"(s))
#define CPCOMMIT()   asm volatile("cp.async.commit_group;\n")
#define CPWAIT2()    asm volatile("cp.async.wait_group 2;\n")

// ---------------- prep: quantize weights (W1 K-permuted), fold BN ----------------
// Permutation within each 32-k chunk: original u32 col c = kk*8 + tig + 4*h
// is stored at p = kk*8 + tig*2 + h, so a B fragment (b0,b1) is one 8-byte load.
__global__ void prep_kernel(const float* __restrict__ W1, const float* __restrict__ W2,
                            const float* __restrict__ gamma, const float* __restrict__ beta,
                            const float* __restrict__ mean, const float* __restrict__ var) {
    int o = blockIdx.x;  // 0..63
    for (int k = threadIdx.x; k < KDIM; k += blockDim.x) {
        float v = (o < NOUT) ? W1[o * KDIM + k] : 0.f;
        __nv_fp8_storage_t f8 = __nv_cvt_float_to_fp8(v, __NV_SATFINITE, __NV_E4M3);
        __half_raw hr = __nv_cvt_fp8_to_halfraw(f8, __NV_E4M3);
        int kt = k >> 5, c32 = k & 31;
        int cu = c32 >> 1, lo = k & 1;
        int kkL = cu >> 3, rem = cu & 7, h = rem >> 2, tig = rem & 3;
        int cup = kkL * 8 + tig * 2 + h;
        g_w1q[o * KDIM + (kt << 5) + (cup << 1) + lo] = __half(hr);
    }
    if (blockIdx.x == 0) {
        for (int i = threadIdx.x; i < 1024; i += blockDim.x) {
            int d = i >> 4, c = i & 15;
            float v = (d < NOUT && c < NCLS) ? W2[c * NOUT + d] : 0.f;
            g_w2f[i] = qf(v);
        }
        if (threadIdx.x < 64) {
            int d = threadIdx.x;
            float inv = 0.f, m = 0.f, b = 0.f;
            if (d < NOUT) {
                inv = gamma[d] / sqrtf(var[d] + 1e-5f);
                m = mean[d];
                b = beta[d];
            }
            g_bn[d] = inv; g_bn[64 + d] = m; g_bn[128 + d] = b;
        }
    }
}

// ---------------- fused kernel ----------------
__global__ void __launch_bounds__(256, 2) fused_kernel(const float* __restrict__ x,
                                                       const float* __restrict__ act_scale,
                                                       float* __restrict__ out) {
    extern __shared__ __align__(16) unsigned char smem[];
    float* xs = reinterpret_cast<float*>(smem);                  // [4][128][32] f32 swizzled
    u32*   ws = reinterpret_cast<u32*>(smem + WS_OFF_BYTES);     // [4][64][20] u32 (f16x2)

    const int t = threadIdx.x;
    const int lane = t & 31, wid = t >> 5;
    const int g = lane >> 2, tig = lane & 3;
    const long long B0 = (long long)blockIdx.x * BM;
    const float s_act = act_scale[0];

    const u32 xs_s = (u32)__cvta_generic_to_shared(xs);
    const u32 ws_s = (u32)__cvta_generic_to_shared(ws);

    auto issue = [&](int kt) {
        int s = kt & 3;
#pragma unroll
        for (int it = 0; it < 4; it++) {
            int i = t + 256 * it;
            int row = i >> 3, c16 = i & 7;
            const float* src = x + (B0 + row) * KDIM + kt * BK + c16 * 4;
            u32 dst = xs_s + s * (XS_STAGE_F32 * 4) + (row * 8 + (c16 ^ (row & 7))) * 16;
            CPA16(dst, src);
        }
        {
            int n = t >> 2, seg = t & 3;
            const __half* src = g_w1q + n * KDIM + kt * BK + seg * 8;
            u32 dst = ws_s + s * (WS_STAGE_U32 * 4) + n * 80 + seg * 16;
            CPA16(dst, src);
        }
    };

    float acc[8][4];
#pragma unroll
    for (int i = 0; i < 8; i++)
#pragma unroll
        for (int j = 0; j < 4; j++) acc[i][j] = 0.f;

    issue(0); CPCOMMIT();
    issue(1); CPCOMMIT();
    issue(2); CPCOMMIT();

    const int r0 = wid * 16 + g;   // (r0 & 7) == g, also for r0+8

#pragma unroll 1
    for (int kt = 0; kt < NCH; kt++) {
        CPWAIT2();
        __syncthreads();
        if (kt + 3 < NCH) issue(kt + 3);
        CPCOMMIT();

        const float* xb = xs + (kt & 3) * XS_STAGE_F32;
        const u32*   wb = ws + (kt & 3) * WS_STAGE_U32;
#pragma unroll
        for (int kk = 0; kk < 2; kk++) {
            u32 a[4];
            {
                int w0 = kk * 16 + tig * 2;
                int u0 = (w0 >> 2) ^ g;
                int u1 = ((w0 >> 2) + 2) ^ g;   // +8 words = +2 units
                int off = w0 & 3;
                float2 v00 = *(const float2*)(xb + (r0 * 8 + u0) * 4 + off);
                float2 v10 = *(const float2*)(xb + ((r0 + 8) * 8 + u0) * 4 + off);
                float2 v01 = *(const float2*)(xb + (r0 * 8 + u1) * 4 + off);
                float2 v11 = *(const float2*)(xb + ((r0 + 8) * 8 + u1) * 4 + off);
                a[0] = q2h(v00.x, v00.y);
                a[1] = q2h(v10.x, v10.y);
                a[2] = q2h(v01.x, v01.y);
                a[3] = q2h(v11.x, v11.y);
            }
#pragma unroll
            for (int ni = 0; ni < 8; ni++) {
                int n = ni * 8 + g;
                uint2 b2 = *(const uint2*)(wb + n * 20 + kk * 8 + tig * 2);
                u32 bb[2] = {b2.x, b2.y};
                mma16816(acc[ni], a, bb);
            }
        }
    }

    // ---- epilogue staging (safe: stage-1 region last read at kt=29, barrier-covered) ----
    __half* aqs = reinterpret_cast<__half*>(smem);            // [128][68] halves
    u32* aqw = reinterpret_cast<u32*>(smem);
    float* w2f = reinterpret_cast<float*>(smem + 17408);      // [64][16]
    float* bni = reinterpret_cast<float*>(smem + 21504);
    float* bnm = bni + 64;
    float* bnb = bni + 128;

    for (int i = t; i < 1024; i += 256) w2f[i] = g_w2f[i];
    if (t < 64) { bni[t] = g_bn[t]; bnm[t] = g_bn[64 + t]; bnb[t] = g_bn[128 + t]; }
    __syncthreads();

    // ---- BN -> ReLU -> uint8 affine quant -> e4m3 quant -> smem ----
#pragma unroll
    for (int ni = 0; ni < 8; ni++) {
        int d0 = ni * 8 + tig * 2;
        float i0 = bni[d0], i1 = bni[d0 + 1];
        float m0 = bnm[d0], m1 = bnm[d0 + 1];
        float e0 = bnb[d0], e1 = bnb[d0 + 1];
#pragma unroll
        for (int v = 0; v < 2; v++) {
            int row = wid * 16 + g + v * 8;
            float h0 = acc[ni][v * 2 + 0];
            float h1 = acc[ni][v * 2 + 1];
            h0 = (h0 - m0) * i0 + e0;
            h1 = (h1 - m1) * i1 + e1;
            h0 = fmaxf(h0, 0.f);
            h1 = fmaxf(h1, 0.f);
            float q0 = fminf(rintf(__fdiv_rn(h0, s_act)), 255.f);  // RNE exact div = jnp.round(x/s)
            float q1 = fminf(rintf(__fdiv_rn(h1, s_act)), 255.f);
            aqw[row * 34 + (d0 >> 1)] = q2h(q0 * s_act, q1 * s_act);
        }
    }
    __syncthreads();

    // ---- GEMM2: out[b, c] = sum_d aq[b][d] * w2q[c][d] ----
    {
        int row = t >> 1;
        int cb = (t & 1) * 6;
        float o2[6] = {0.f, 0.f, 0.f, 0.f, 0.f, 0.f};
#pragma unroll 1
        for (int d = 0; d < NOUT; d++) {
            float av = __half2float(aqs[row * 68 + d]);
#pragma unroll
            for (int j = 0; j < 6; j++) o2[j] = fmaf(av, w2f[d * 16 + cb + j], o2[j]);
        }
#pragma unroll
        for (int j = 0; j < 6; j++) out[(B0 + row) * NCLS + cb + j] = o2[j];
    }
}

// ---------------- launch ----------------
extern "C" void kernel_launch(void* const* d_in, const int* in_sizes, int n_in,
                              void* d_out, int out_size) {
    const float* x      = (const float*)d_in[0];
    const float* W1     = (const float*)d_in[1];
    const float* W2     = (const float*)d_in[2];
    const float* gammaP = (const float*)d_in[3];
    const float* betaP  = (const float*)d_in[4];
    const float* meanP  = (const float*)d_in[5];
    const float* varP   = (const float*)d_in[6];
    const float* ascale = (const float*)d_in[7];
    float* out = (float*)d_out;

    int B = in_sizes[0] / KDIM;  // 65536

    cudaFuncSetAttribute(fused_kernel, cudaFuncAttributeMaxDynamicSharedMemorySize, SMEM_BYTES);
    prep_kernel<<<64, 256>>>(W1, W2, gammaP, betaP, meanP, varP);
    fused_kernel<<<B / BM, 256, SMEM_BYTES>>>(x, ascale, out);
}

// round 3
// speedup vs baseline: 1.0887x; 1.0887x over previous
#include <cuda_runtime.h>
#include <cuda_fp16.h>
#include <cuda_fp8.h>
#include <cstdint>

using u32 = unsigned int;

#define BM   128
#define KDIM 1024
#define NOUT 58
#define NCLS 12

// ---------------- device scratch (no allocations allowed) ----------------
__device__ __half g_w1q[64 * 1024];   // e4m3-valued W1 as f16, rows 58..63 zero
__device__ float  g_w2f[64 * 16];     // e4m3-valued W2 transposed [d][c], zero padded
__device__ float  g_bn[3 * 64];       // [inv | mean | beta], zero padded

// ---------------- helpers ----------------
__device__ __forceinline__ u32 q2h(float a, float b) {
    __nv_fp8x2_storage_t f8 =
        __nv_cvt_float2_to_fp8x2(make_float2(a, b), __NV_SATFINITE, __NV_E4M3);
    __half2_raw h2 = __nv_cvt_fp8x2_to_halfraw2(f8, __NV_E4M3);
    return (u32)h2.x | ((u32)h2.y << 16);
}

__device__ __forceinline__ float qf(float a) {
    __nv_fp8_storage_t f8 = __nv_cvt_float_to_fp8(a, __NV_SATFINITE, __NV_E4M3);
    __half_raw hr = __nv_cvt_fp8_to_halfraw(f8, __NV_E4M3);
    return __half2float(__half(hr));
}

__device__ __forceinline__ void mma16816(float* c, const u32* a, const u32* b) {
    asm volatile(
        "mma.sync.aligned.m16n8k16.row.col.f32.f16.f16.f32 "
        "{%0,%1,%2,%3}, {%4,%5,%6,%7}, {%8,%9}, {%0,%1,%2,%3};\n"
        : "+f"(c[0]), "+f"(c[1]), "+f"(c[2]), "+f"(c[3])
        : "r"(a[0]), "r"(a[1]), "r"(a[2]), "r"(a[3]), "r"(b[0]), "r"(b[1]));
}

#define CPA16(d, s)  asm volatile("cp.async.cg.shared.global [%0], [%1], 16;\n" :: "r"(d), "l"(s))
#define CPCOMMIT()   asm volatile("cp.async.commit_group;\n")
#define CPWAIT0()    asm volatile("cp.async.wait_group 0;\n")

// ---------------- prep: quantize weights, fold BN ----------------
__global__ void prep_kernel(const float* __restrict__ W1, const float* __restrict__ W2,
                            const float* __restrict__ gamma, const float* __restrict__ beta,
                            const float* __restrict__ mean, const float* __restrict__ var) {
    int o = blockIdx.x;  // 0..63
    for (int k = threadIdx.x; k < KDIM; k += blockDim.x) {
        float v = (o < NOUT) ? W1[o * KDIM + k] : 0.f;
        __nv_fp8_storage_t f8 = __nv_cvt_float_to_fp8(v, __NV_SATFINITE, __NV_E4M3);
        __half_raw hr = __nv_cvt_fp8_to_halfraw(f8, __NV_E4M3);
        g_w1q[o * KDIM + k] = __half(hr);
    }
    if (blockIdx.x == 0) {
        for (int i = threadIdx.x; i < 1024; i += blockDim.x) {
            int d = i >> 4, c = i & 15;
            float v = (d < NOUT && c < NCLS) ? W2[c * NOUT + d] : 0.f;
            g_w2f[i] = qf(v);
        }
        if (threadIdx.x < 64) {
            int d = threadIdx.x;
            float inv = 0.f, m = 0.f, b = 0.f;
            if (d < NOUT) {
                inv = gamma[d] / sqrtf(var[d] + 1e-5f);
                m = mean[d];
                b = beta[d];
            }
            g_bn[d] = inv; g_bn[64 + d] = m; g_bn[128 + d] = b;
        }
    }
}

// ---------------- fused: quant -> GEMM1 (tensor cores) -> BN/ReLU/uq/quant -> GEMM2 ----------------
__global__ void __launch_bounds__(256, 3) fused_kernel(const float* __restrict__ x,
                                                       const float* __restrict__ act_scale,
                                                       float* __restrict__ out) {
    // phase 1: xs u32[2][128][32] @0 (32KB), ws u32[2][64][32] @32768 (16KB) = 48KB
    // phase 2 (reuse): aqs half[128][68] @0, w2f f32[64][16] @17408, bn @21504
    __shared__ __align__(16) unsigned char smem[49152];
    u32* xsw = reinterpret_cast<u32*>(smem);
    u32* wsw = reinterpret_cast<u32*>(smem + 32768);

    const int t = threadIdx.x;
    const int lane = t & 31, wid = t >> 5;
    const int wm = wid >> 1, wn = wid & 1;   // 4x2 warp grid, 32x32 per warp
    const int g = lane >> 2, tig = lane & 3;
    const long long B0 = (long long)blockIdx.x * BM;
    const u32 ws_s = (u32)__cvta_generic_to_shared(wsw);

    float acc[2][4][4];
#pragma unroll
    for (int i = 0; i < 2; i++)
#pragma unroll
        for (int j = 0; j < 4; j++)
#pragma unroll
            for (int k = 0; k < 4; k++) acc[i][j][k] = 0.f;

    float4 xr[4];
    const float4* xg = reinterpret_cast<const float4*>(x);

    auto load_half = [&](int kt, int h) {
#pragma unroll
        for (int it = 0; it < 4; it++) {
            int i = t + 256 * (it + 4 * h);
            int row = i >> 4, c4 = i & 15;
            xr[it] = xg[(B0 + row) * 256 + kt * 16 + c4];
        }
    };

    auto store_half = [&](int buf, int h) {
        u32* xb = xsw + buf * (128 * 32);
#pragma unroll
        for (int it = 0; it < 4; it++) {
            int i = t + 256 * (it + 4 * h);
            int row = i >> 4, c4 = i & 15;
            uint2 v;
            v.x = q2h(xr[it].x, xr[it].y);
            v.y = q2h(xr[it].z, xr[it].w);
            int idx = row * 32 + ((c4 * 2) ^ (4 * (row & 7)));  // XOR swizzle
            *reinterpret_cast<uint2*>(xb + idx) = v;
        }
    };

    auto issueW = [&](int kt, int buf) {
#pragma unroll
        for (int it = 0; it < 2; it++) {
            int fi = t + 256 * it;
            int n = fi >> 3, seg = fi & 7;
            const __half* src = g_w1q + n * KDIM + kt * 64 + seg * 8;
            u32 dst = ws_s + (buf * (64 * 32) + n * 32 + ((seg * 4) ^ (4 * (n & 7)))) * 4;
            CPA16(dst, src);
        }
        CPCOMMIT();
    };

    auto compute2 = [&](int buf, int kk0) {
        const u32* xb = xsw + buf * (128 * 32);
        const u32* wb = wsw + buf * (64 * 32);
#pragma unroll
        for (int kx = 0; kx < 2; kx++) {
            int kk = kk0 + kx;
            u32 a[2][4], b[4][2];
#pragma unroll
            for (int mi = 0; mi < 2; mi++) {
                int r0 = wm * 32 + mi * 16 + g;     // (r0 & 7) == g
                int sw = 4 * g;
                int w0 = (kk * 8 + tig) ^ sw;
                int w1 = (kk * 8 + tig + 4) ^ sw;
                a[mi][0] = xb[r0 * 32 + w0];
                a[mi][1] = xb[(r0 + 8) * 32 + w0];
                a[mi][2] = xb[r0 * 32 + w1];
                a[mi][3] = xb[(r0 + 8) * 32 + w1];
            }
#pragma unroll
            for (int ni = 0; ni < 4; ni++) {
                int n = wn * 32 + ni * 8 + g;       // (n & 7) == g
                int sw = 4 * g;
                b[ni][0] = wb[n * 32 + ((kk * 8 + tig) ^ sw)];
                b[ni][1] = wb[n * 32 + ((kk * 8 + tig + 4) ^ sw)];
            }
#pragma unroll
            for (int mi = 0; mi < 2; mi++)
#pragma unroll
                for (int ni = 0; ni < 4; ni++) mma16816(acc[mi][ni], a[mi], b[ni]);
        }
    };

    // ---- prologue: fill buffer 0 ----
    issueW(0, 0);
    load_half(0, 0); store_half(0, 0);
    load_half(0, 1); store_half(0, 1);
    CPWAIT0();
    __syncthreads();

    // ---- mainloop: 16 chunks of K=64, double buffered, split prefetch ----
#pragma unroll 1
    for (int kt = 0; kt < 16; kt++) {
        int buf = kt & 1;
        if (kt < 15) { issueW(kt + 1, buf ^ 1); load_half(kt + 1, 0); }
        compute2(buf, 0);
        if (kt < 15) { store_half(buf ^ 1, 0); load_half(kt + 1, 1); }
        compute2(buf, 2);
        if (kt < 15) { store_half(buf ^ 1, 1); }
        CPWAIT0();
        __syncthreads();
    }

    // ---- epilogue: BN -> ReLU -> uint8 affine quant -> e4m3 quant -> smem ----
    __half* aqs = reinterpret_cast<__half*>(smem);          // [128][68] halves
    u32* aqw = reinterpret_cast<u32*>(smem);
    float* w2f = reinterpret_cast<float*>(smem + 17408);    // [64][16]
    float* bni = reinterpret_cast<float*>(smem + 21504);
    float* bnm = bni + 64;
    float* bnb = bni + 128;

    for (int i = t; i < 1024; i += 256) w2f[i] = g_w2f[i];
    if (t < 64) { bni[t] = g_bn[t]; bnm[t] = g_bn[64 + t]; bnb[t] = g_bn[128 + t]; }
    const float s_act = act_scale[0];
    __syncthreads();

#pragma unroll
    for (int mi = 0; mi < 2; mi++) {
#pragma unroll
        for (int ni = 0; ni < 4; ni++) {
            int d0 = wn * 32 + ni * 8 + tig * 2;
            float i0 = bni[d0], i1 = bni[d0 + 1];
            float m0 = bnm[d0], m1 = bnm[d0 + 1];
            float e0 = bnb[d0], e1 = bnb[d0 + 1];
            int rA = wm * 32 + mi * 16 + g;
#pragma unroll
            for (int v = 0; v < 2; v++) {
                int row = rA + v * 8;
                float h0 = acc[mi][ni][v * 2 + 0];
                float h1 = acc[mi][ni][v * 2 + 1];
                h0 = (h0 - m0) * i0 + e0;
                h1 = (h1 - m1) * i1 + e1;
                h0 = fmaxf(h0, 0.f);
                h1 = fmaxf(h1, 0.f);
                float r0 = fminf(rintf(__fdiv_rn(h0, s_act)), 255.f);  // RNE, exact div = jnp.round(x/s)
                float r1 = fminf(rintf(__fdiv_rn(h1, s_act)), 255.f);
                aqw[row * 34 + (d0 >> 1)] = q2h(r0 * s_act, r1 * s_act);
            }
        }
    }
    __syncthreads();

    // ---- GEMM2: out[b, c] = sum_d aq[b][d] * w2q[c][d], 12 cols ----
    {
        int row = t >> 1;
        int cb = (t & 1) * 6;
        float o2[6] = {0.f, 0.f, 0.f, 0.f, 0.f, 0.f};
#pragma unroll 1
        for (int d = 0; d < NOUT; d++) {
            float av = __half2float(aqs[row * 68 + d]);
#pragma unroll
            for (int j = 0; j < 6; j++) o2[j] = fmaf(av, w2f[d * 16 + cb + j], o2[j]);
        }
#pragma unroll
        for (int j = 0; j < 6; j++) out[(B0 + row) * NCLS + cb + j] = o2[j];
    }
}

// ---------------- launch ----------------
extern "C" void kernel_launch(void* const* d_in, const int* in_sizes, int n_in,
                              void* d_out, int out_size) {
    const float* x      = (const float*)d_in[0];
    const float* W1     = (const float*)d_in[1];
    const float* W2     = (const float*)d_in[2];
    const float* gammaP = (const float*)d_in[3];
    const float* betaP  = (const float*)d_in[4];
    const float* meanP  = (const float*)d_in[5];
    const float* varP   = (const float*)d_in[6];
    const float* ascale = (const float*)d_in[7];
    float* out = (float*)d_out;

    int B = in_sizes[0] / KDIM;  // 65536

    prep_kernel<<<64, 256>>>(W1, W2, gammaP, betaP, meanP, varP);
    fused_kernel<<<B / BM, 256>>>(x, ascale, out);
}